// round 1
// baseline (speedup 1.0000x reference)
#include <cuda_runtime.h>
#include <math.h>

// Problem constants
#define Bdim 2
#define Tdim 1536
#define Cdim 1536
#define Hdim 8
#define Kdim 64
#define Vdim 192
#define HK   512      // Hdim*Kdim
#define HV   1536     // Hdim*Vdim
#define L2   3071     // 2*T-1

// ---------------- scratch (device globals; no runtime allocation) ----------------
__device__ float g_qw[(size_t)Bdim * Hdim * Tdim * Kdim];   // (q*scale + r_w_bias)  [b,h,t,k]
__device__ float g_qr[(size_t)Bdim * Hdim * Tdim * Kdim];   // (q*scale + r_r_bias)  [b,h,t,k]
__device__ float g_k [(size_t)Bdim * Hdim * Tdim * Kdim];   // k                     [b,h,t,k]
__device__ float g_v [(size_t)Bdim * Hdim * Tdim * Vdim];   // v                     [b,h,t,v]
__device__ float g_rk[(size_t)Hdim * L2 * Kdim];            // rk                    [h,r,k]
__device__ float g_logits[(size_t)Bdim * Hdim * Tdim * Tdim]; // logits / P          [b,h,t,s]
__device__ float g_attn[(size_t)Bdim * Tdim * HV];          // attention output      [b,t,h*V+v]

// ---------------- generic 64x64 tiled SGEMM with mode-specific epilogues ---------
// MODE 0: Q projection  -> g_qw, g_qr  (scale by K^-0.5, add biases)
// MODE 1: K projection  -> g_k
// MODE 2: V projection  -> g_v
// MODE 3: output proj   A = g_attn, B = Wo, +bo -> d_out
// MODE 4: P @ V (batched over b*h): A = g_logits[z], B = g_v[z] -> g_attn
template <int MODE>
__global__ void gemm64(const float* __restrict__ A, const float* __restrict__ Bw,
                       const float* __restrict__ bias0, const float* __restrict__ bias1,
                       float* __restrict__ out,
                       int M, int N, int Kc, int lda, int ldb)
{
    __shared__ float As[16][65];   // [k][m] transposed, padded
    __shared__ float Bs[16][65];   // [k][n]

    const int z  = blockIdx.z;
    const int m0 = blockIdx.y * 64;
    const int n0 = blockIdx.x * 64;
    const int tx = threadIdx.x, ty = threadIdx.y;
    const int tid = ty * 16 + tx;

    const float* Ap;
    const float* Bp;
    if (MODE == 4) {
        Ap = g_logits + (size_t)z * Tdim * Tdim;
        Bp = g_v      + (size_t)z * Tdim * Vdim;
    } else if (MODE == 3) {
        Ap = g_attn;
        Bp = Bw;
    } else {
        Ap = A;
        Bp = Bw;
    }

    float acc[4][4] = {};

    for (int kc = 0; kc < Kc; kc += 16) {
        #pragma unroll
        for (int i = 0; i < 4; i++) {
            int l = tid + i * 256;
            int r = l >> 4, c = l & 15;
            As[c][r] = Ap[(size_t)(m0 + r) * lda + kc + c];
        }
        #pragma unroll
        for (int i = 0; i < 4; i++) {
            int l = tid + i * 256;
            int r = l >> 6, c = l & 63;
            Bs[r][c] = Bp[(size_t)(kc + r) * ldb + n0 + c];
        }
        __syncthreads();

        #pragma unroll
        for (int k = 0; k < 16; k++) {
            float a[4], b[4];
            #pragma unroll
            for (int i = 0; i < 4; i++) a[i] = As[k][ty * 4 + i];
            #pragma unroll
            for (int j = 0; j < 4; j++) b[j] = Bs[k][tx * 4 + j];
            #pragma unroll
            for (int i = 0; i < 4; i++)
                #pragma unroll
                for (int j = 0; j < 4; j++)
                    acc[i][j] += a[i] * b[j];
        }
        __syncthreads();
    }

    #pragma unroll
    for (int i = 0; i < 4; i++) {
        int m = m0 + ty * 4 + i;
        #pragma unroll
        for (int j = 0; j < 4; j++) {
            int n = n0 + tx * 4 + j;
            float cval = acc[i][j];
            if (MODE == 0) {
                int b = m / Tdim, t = m % Tdim;
                int h = n >> 6, kk = n & 63;
                float vq = cval * 0.125f;  // K^-0.5 = 1/8
                size_t idx = ((size_t)(b * Hdim + h) * Tdim + t) * Kdim + kk;
                g_qw[idx] = vq + bias0[n];
                g_qr[idx] = vq + bias1[n];
            } else if (MODE == 1) {
                int b = m / Tdim, t = m % Tdim;
                int h = n >> 6, kk = n & 63;
                g_k[((size_t)(b * Hdim + h) * Tdim + t) * Kdim + kk] = cval;
            } else if (MODE == 2) {
                int b = m / Tdim, t = m % Tdim;
                int h = n / Vdim, vv = n % Vdim;
                g_v[((size_t)(b * Hdim + h) * Tdim + t) * Vdim + vv] = cval;
            } else if (MODE == 3) {
                out[(size_t)m * HV + n] = cval + bias0[n];
            } else { // MODE 4
                int b = z / Hdim, h = z % Hdim;
                g_attn[((size_t)(b * Tdim + m)) * HV + h * Vdim + n] = cval;
            }
        }
    }
}

// ---------------- positional features @ Wr -> g_rk [h,r,k] -----------------------
__global__ void rk_kernel(const float* __restrict__ Wr)
{
    int r = blockIdx.x;       // 0..L2-1
    int n = threadIdx.x;      // 0..511
    float d  = (float)(r - (Tdim - 1));
    float ad = fabsf(d);
    float sg = (d > 0.f) ? 1.f : ((d < 0.f) ? -1.f : 0.f);
    // pow_rate computed in double (matches np.exp(np.log(T+1)/nb)), then f32 powers
    float pr = (float)exp(log((double)(Tdim + 1)) / 16.0);
    float acc = 0.f;
    #pragma unroll
    for (int i = 0; i < 16; i++) {
        float cw = powf(pr, (float)(i + 1)) - 1.0f;
        if (cw > ad)
            acc += Wr[i * HK + n] + sg * Wr[(i + 16) * HK + n];
    }
    int h = n >> 6, kk = n & 63;
    g_rk[((size_t)h * L2 + r) * Kdim + kk] = acc;
}

// ---------------- fused content + relative logits ---------------------------------
// logits[b,h,t,s] = (q*scale + r_w)·k_s + (q*scale + r_r)·rk[s - t + T - 1]
__global__ void logits_kernel()
{
    __shared__ float qw_s[64][17];
    __shared__ float qr_s[64][17];
    __shared__ float ks_s[64][17];
    __shared__ float rk_s[127][17];

    const int bh = blockIdx.z;
    const int t0 = blockIdx.y * 64;
    const int s0 = blockIdx.x * 64;
    const int h  = bh % Hdim;
    const int tx = threadIdx.x, ty = threadIdx.y;
    const int tid = ty * 16 + tx;

    const float* qwp = g_qw + (size_t)bh * Tdim * Kdim;
    const float* qrp = g_qr + (size_t)bh * Tdim * Kdim;
    const float* kp  = g_k  + (size_t)bh * Tdim * Kdim;
    const float* rkp = g_rk + (size_t)h  * L2   * Kdim;

    const int band_base = s0 - t0 - 63 + (Tdim - 1);  // rk row for band row 0 (always in range)

    float acc[4][4] = {};

    for (int kk = 0; kk < Kdim; kk += 16) {
        #pragma unroll
        for (int i = 0; i < 4; i++) {
            int l = tid + i * 256;
            int r = l >> 4, c = l & 15;
            qw_s[r][c] = qwp[(size_t)(t0 + r) * Kdim + kk + c];
            qr_s[r][c] = qrp[(size_t)(t0 + r) * Kdim + kk + c];
            ks_s[r][c] = kp [(size_t)(s0 + r) * Kdim + kk + c];
        }
        for (int l = tid; l < 127 * 16; l += 256) {
            int r = l >> 4, c = l & 15;
            rk_s[r][c] = rkp[(size_t)(band_base + r) * Kdim + kk + c];
        }
        __syncthreads();

        #pragma unroll
        for (int k = 0; k < 16; k++) {
            float aw[4], ar[4], bk[4];
            #pragma unroll
            for (int i = 0; i < 4; i++) { aw[i] = qw_s[ty * 4 + i][k]; ar[i] = qr_s[ty * 4 + i][k]; }
            #pragma unroll
            for (int j = 0; j < 4; j++) bk[j] = ks_s[tx * 4 + j][k];
            const int d0 = tx * 4 - ty * 4 + 63;
            #pragma unroll
            for (int i = 0; i < 4; i++)
                #pragma unroll
                for (int j = 0; j < 4; j++)
                    acc[i][j] += aw[i] * bk[j] + ar[i] * rk_s[d0 + j - i][k];
        }
        __syncthreads();
    }

    #pragma unroll
    for (int i = 0; i < 4; i++) {
        int t = t0 + ty * 4 + i;
        #pragma unroll
        for (int j = 0; j < 4; j++) {
            int s = s0 + tx * 4 + j;
            g_logits[((size_t)bh * Tdim + t) * Tdim + s] = acc[i][j];
        }
    }
}

// ---------------- row softmax over s (T=1536), in-place on g_logits --------------
__global__ void softmax_kernel()
{
    const size_t row = blockIdx.x;          // bh*T + t
    float* p = g_logits + row * Tdim;
    const int tid = threadIdx.x;            // 256 threads, 6 elems each

    float v[6];
    float m = -INFINITY;
    #pragma unroll
    for (int e = 0; e < 6; e++) { v[e] = p[tid + e * 256]; m = fmaxf(m, v[e]); }

    __shared__ float red[256];
    red[tid] = m; __syncthreads();
    for (int s = 128; s > 0; s >>= 1) {
        if (tid < s) red[tid] = fmaxf(red[tid], red[tid + s]);
        __syncthreads();
    }
    m = red[0]; __syncthreads();

    float sum = 0.f;
    #pragma unroll
    for (int e = 0; e < 6; e++) { v[e] = expf(v[e] - m); sum += v[e]; }
    red[tid] = sum; __syncthreads();
    for (int s = 128; s > 0; s >>= 1) {
        if (tid < s) red[tid] += red[tid + s];
        __syncthreads();
    }
    float inv = 1.0f / red[0];
    #pragma unroll
    for (int e = 0; e < 6; e++) p[tid + e * 256] = v[e] * inv;
}

// ---------------- launch ----------------------------------------------------------
extern "C" void kernel_launch(void* const* d_in, const int* in_sizes, int n_in,
                              void* d_out, int out_size)
{
    const float* x   = (const float*)d_in[0];
    const float* Wq  = (const float*)d_in[1];
    const float* Wk  = (const float*)d_in[2];
    const float* Wv  = (const float*)d_in[3];
    const float* Wr  = (const float*)d_in[4];
    const float* rwb = (const float*)d_in[5];   // (1,H,1,K) -> [512]
    const float* rrb = (const float*)d_in[6];
    const float* Wo  = (const float*)d_in[7];
    const float* bo  = (const float*)d_in[8];
    float* out = (float*)d_out;

    dim3 blk(16, 16);
    const int M = Bdim * Tdim;  // 3072

    // projections
    gemm64<0><<<dim3(HK / 64, M / 64, 1), blk>>>(x, Wq, rwb, rrb, nullptr, M, HK, Cdim, Cdim, HK);
    gemm64<1><<<dim3(HK / 64, M / 64, 1), blk>>>(x, Wk, nullptr, nullptr, nullptr, M, HK, Cdim, Cdim, HK);
    gemm64<2><<<dim3(HV / 64, M / 64, 1), blk>>>(x, Wv, nullptr, nullptr, nullptr, M, HV, Cdim, Cdim, HV);

    // positional embedding projection
    rk_kernel<<<L2, HK>>>(Wr);

    // fused content + relative logits
    logits_kernel<<<dim3(Tdim / 64, Tdim / 64, Bdim * Hdim), blk>>>();

    // softmax
    softmax_kernel<<<Bdim * Hdim * Tdim, 256>>>();

    // P @ V  (batched over b*h)
    gemm64<4><<<dim3(Vdim / 64, Tdim / 64, Bdim * Hdim), blk>>>(nullptr, nullptr, nullptr, nullptr, nullptr,
                                                                Tdim, Vdim, Tdim, Tdim, Vdim);

    // output projection + bias
    gemm64<3><<<dim3(HV / 64, M / 64, 1), blk>>>(nullptr, Wo, bo, nullptr, out, M, HV, HV, HV, HV);
}

// round 4
// speedup vs baseline: 1.9875x; 1.9875x over previous
#include <cuda_runtime.h>
#include <cuda_bf16.h>
#include <stdint.h>
#include <math.h>

// Problem constants
#define Bdim 2
#define Tdim 1536
#define Cdim 1536
#define Hdim 8
#define Kdim 64
#define Vdim 192
#define HK   512
#define HV   1536
#define L2   3071     // 2*T-1

// ---------------- scratch ----------------
__device__ float g_qw[(size_t)Bdim * Hdim * Tdim * Kdim];
__device__ float g_qr[(size_t)Bdim * Hdim * Tdim * Kdim];
__device__ float g_k [(size_t)Bdim * Hdim * Tdim * Kdim];
__device__ float g_v [(size_t)Bdim * Hdim * Tdim * Vdim];
__device__ float g_rk[(size_t)Hdim * L2 * Kdim];
__device__ float g_logits[(size_t)Bdim * Hdim * Tdim * Tdim];
__device__ float g_attn[(size_t)Bdim * Tdim * HV];

// pack two floats to bf16x2 (a -> low half, b -> high half)
__device__ __forceinline__ uint32_t pack2(float a, float b) {
    uint32_t r;
    asm("cvt.rn.bf16x2.f32 %0, %1, %2;" : "=r"(r) : "f"(b), "f"(a));
    return r;
}
// split pair of floats into bf16 hi + bf16 lo packed words
__device__ __forceinline__ void split2(float x0, float x1, uint32_t& h, uint32_t& l) {
    float h0 = __bfloat162float(__float2bfloat16(x0));
    float h1 = __bfloat162float(__float2bfloat16(x1));
    h = pack2(h0, h1);
    l = pack2(x0 - h0, x1 - h1);
}

__device__ __forceinline__ void mma_bf16(float* d, const uint32_t* a, const uint32_t* b) {
    asm volatile(
        "mma.sync.aligned.m16n8k16.row.col.f32.bf16.bf16.f32 "
        "{%0,%1,%2,%3}, {%4,%5,%6,%7}, {%8,%9}, {%0,%1,%2,%3};"
        : "+f"(d[0]), "+f"(d[1]), "+f"(d[2]), "+f"(d[3])
        : "r"(a[0]), "r"(a[1]), "r"(a[2]), "r"(a[3]), "r"(b[0]), "r"(b[1]));
}

// ---------------- bf16x3 tensor-core GEMM, 128x64x16 tiles, 8 warps ----------------
// MODE 0: Q proj -> g_qw,g_qr  | 1: K proj | 2: V proj | 3: out proj + bo -> d_out
// MODE 4: P @ V -> g_attn | 5: content logits -> g_logits | 6: rel logits scatter-add
template <int MODE, bool BT>
__global__ __launch_bounds__(256) void mma_gemm(
    const float* __restrict__ Aext, const float* __restrict__ Bext,
    const float* __restrict__ bias0, const float* __restrict__ bias1,
    float* __restrict__ outp, int Kc, int lda, int ldb)
{
    // [row][kpair] packed bf16x2, stride 12 words (8 pairs + pad) -> conflict-free frags
    __shared__ uint32_t As_hi[128 * 12], As_lo[128 * 12];
    __shared__ uint32_t Bs_hi[64 * 12],  Bs_lo[64 * 12];

    const int z   = blockIdx.z;
    const int m0  = blockIdx.y * 128;
    const int n0  = blockIdx.x * 64;
    const int tid = threadIdx.x;
    const int lane = tid & 31, warp = tid >> 5;
    const int wm = warp >> 1, wn = warp & 1;

    const float* Ap;
    const float* Bp;
    if (MODE == 5)      { Ap = g_qw + (size_t)z * Tdim * Kdim; Bp = g_k  + (size_t)z * Tdim * Kdim; }
    else if (MODE == 6) { Ap = g_qr + (size_t)z * Tdim * Kdim; Bp = g_rk + (size_t)(z & 7) * L2 * Kdim; }
    else if (MODE == 4) { Ap = g_logits + (size_t)z * Tdim * Tdim; Bp = g_v + (size_t)z * Tdim * Vdim; }
    else if (MODE == 3) { Ap = g_attn; Bp = Bext; }
    else                { Ap = Aext; Bp = Bext; }

    const int rbase = (MODE == 6) ? (1408 - m0 + n0) : n0;   // B-row base (r-space for MODE 6)

    float acc[2][4][4] = {};

    for (int kc = 0; kc < Kc; kc += 16) {
        // ---- A tile: 128 rows x 16 k ----
        #pragma unroll
        for (int it = 0; it < 2; it++) {
            int idx = tid + it * 256;
            int row = idx >> 2, q = idx & 3;                 // q: which 4-k group
            float4 v = *(const float4*)(Ap + (size_t)(m0 + row) * lda + kc + q * 4);
            uint32_t h0, l0, h1, l1;
            split2(v.x, v.y, h0, l0);
            split2(v.z, v.w, h1, l1);
            As_hi[row * 12 + q * 2]     = h0;
            As_hi[row * 12 + q * 2 + 1] = h1;
            As_lo[row * 12 + q * 2]     = l0;
            As_lo[row * 12 + q * 2 + 1] = l1;
        }
        // ---- B tile: 64 n-rows x 16 k (always [n][kpair] in smem) ----
        if (BT) {
            int row = tid >> 2, q = tid & 3;
            int gr = rbase + row;
            if (MODE == 6 && gr > L2 - 1) gr = L2 - 1;
            float4 v = *(const float4*)(Bp + (size_t)gr * ldb + kc + q * 4);
            uint32_t h0, l0, h1, l1;
            split2(v.x, v.y, h0, l0);
            split2(v.z, v.w, h1, l1);
            Bs_hi[row * 12 + q * 2]     = h0;
            Bs_hi[row * 12 + q * 2 + 1] = h1;
            Bs_lo[row * 12 + q * 2]     = l0;
            Bs_lo[row * 12 + q * 2 + 1] = l1;
        } else {
            int n = tid & 63, q = tid >> 6;                  // q: 4-k group
            const float* bp = Bp + (size_t)(kc + q * 4) * ldb + n0 + n;
            float x0 = bp[0];
            float x1 = bp[(size_t)ldb];
            float x2 = bp[(size_t)2 * ldb];
            float x3 = bp[(size_t)3 * ldb];
            uint32_t h0, l0, h1, l1;
            split2(x0, x1, h0, l0);
            split2(x2, x3, h1, l1);
            Bs_hi[n * 12 + q * 2]     = h0;
            Bs_hi[n * 12 + q * 2 + 1] = h1;
            Bs_lo[n * 12 + q * 2]     = l0;
            Bs_lo[n * 12 + q * 2 + 1] = l1;
        }
        __syncthreads();

        // ---- fragments + 3-pass mma ----
        const int kp  = lane & 3;
        const int ar0 = wm * 32 + (lane >> 2);
        uint32_t ah[2][4], al[2][4], bh[4][2], bl[4][2];
        #pragma unroll
        for (int mi = 0; mi < 2; mi++) {
            int r = ar0 + mi * 16;
            ah[mi][0] = As_hi[r * 12 + kp];       ah[mi][1] = As_hi[(r + 8) * 12 + kp];
            ah[mi][2] = As_hi[r * 12 + kp + 4];   ah[mi][3] = As_hi[(r + 8) * 12 + kp + 4];
            al[mi][0] = As_lo[r * 12 + kp];       al[mi][1] = As_lo[(r + 8) * 12 + kp];
            al[mi][2] = As_lo[r * 12 + kp + 4];   al[mi][3] = As_lo[(r + 8) * 12 + kp + 4];
        }
        #pragma unroll
        for (int ni = 0; ni < 4; ni++) {
            int n = wn * 32 + ni * 8 + (lane >> 2);
            bh[ni][0] = Bs_hi[n * 12 + kp];  bh[ni][1] = Bs_hi[n * 12 + kp + 4];
            bl[ni][0] = Bs_lo[n * 12 + kp];  bl[ni][1] = Bs_lo[n * 12 + kp + 4];
        }
        #pragma unroll
        for (int mi = 0; mi < 2; mi++)
            #pragma unroll
            for (int ni = 0; ni < 4; ni++) {
                mma_bf16(acc[mi][ni], ah[mi], bh[ni]);
                mma_bf16(acc[mi][ni], ah[mi], bl[ni]);
                mma_bf16(acc[mi][ni], al[mi], bh[ni]);
            }
        __syncthreads();
    }

    // ---------------- epilogue ----------------
    #pragma unroll
    for (int mi = 0; mi < 2; mi++) {
        #pragma unroll
        for (int ni = 0; ni < 4; ni++) {
            #pragma unroll
            for (int hh = 0; hh < 2; hh++) {
                const int row = m0 + wm * 32 + mi * 16 + (lane >> 2) + hh * 8;
                const int col = rbase + wn * 32 + ni * 8 + 2 * (lane & 3);
                float v0 = acc[mi][ni][hh * 2 + 0];
                float v1 = acc[mi][ni][hh * 2 + 1];

                if (MODE == 0) {
                    int bb = row / Tdim, t = row % Tdim;
                    int h = col >> 6, kk = col & 63;
                    size_t idx = (((size_t)bb * Hdim + h) * Tdim + t) * Kdim + kk;
                    float q0 = v0 * 0.125f, q1 = v1 * 0.125f;
                    *(float2*)&g_qw[idx] = make_float2(q0 + bias0[col], q1 + bias0[col + 1]);
                    *(float2*)&g_qr[idx] = make_float2(q0 + bias1[col], q1 + bias1[col + 1]);
                } else if (MODE == 1) {
                    int bb = row / Tdim, t = row % Tdim;
                    int h = col >> 6, kk = col & 63;
                    *(float2*)&g_k[(((size_t)bb * Hdim + h) * Tdim + t) * Kdim + kk] = make_float2(v0, v1);
                } else if (MODE == 2) {
                    int bb = row / Tdim, t = row % Tdim;
                    int h = col / Vdim, vv = col % Vdim;
                    *(float2*)&g_v[(((size_t)bb * Hdim + h) * Tdim + t) * Vdim + vv] = make_float2(v0, v1);
                } else if (MODE == 3) {
                    *(float2*)&outp[(size_t)row * HV + col] = make_float2(v0 + bias0[col], v1 + bias0[col + 1]);
                } else if (MODE == 4) {
                    int bb = z >> 3, h = z & 7;
                    *(float2*)&g_attn[((size_t)(bb * Tdim + row)) * HV + h * Vdim + col] = make_float2(v0, v1);
                } else if (MODE == 5) {
                    *(float2*)&g_logits[((size_t)z * Tdim + row) * Tdim + col] = make_float2(v0, v1);
                } else { // MODE 6: scatter-add  s = r + t - (T-1)
                    float* pl = g_logits + ((size_t)z * Tdim + row) * Tdim;
                    int s0 = col + row - (Tdim - 1);
                    if (s0 >= 0 && s0 < Tdim) pl[s0] += v0;
                    if (s0 + 1 >= 0 && s0 + 1 < Tdim) pl[s0 + 1] += v1;
                }
            }
        }
    }
}

// ---------------- positional features @ Wr -> g_rk [h,r,k] -----------------------
__global__ void rk_kernel(const float* __restrict__ Wr)
{
    __shared__ float cw[16];
    int r = blockIdx.x;
    int n = threadIdx.x;
    if (threadIdx.x < 16) {
        float pr = (float)exp(log((double)(Tdim + 1)) / 16.0);
        cw[threadIdx.x] = powf(pr, (float)(threadIdx.x + 1)) - 1.0f;
    }
    __syncthreads();
    float d  = (float)(r - (Tdim - 1));
    float ad = fabsf(d);
    float sg = (d > 0.f) ? 1.f : ((d < 0.f) ? -1.f : 0.f);
    float acc = 0.f;
    #pragma unroll
    for (int i = 0; i < 16; i++)
        if (cw[i] > ad)
            acc += Wr[i * HK + n] + sg * Wr[(i + 16) * HK + n];
    int h = n >> 6, kk = n & 63;
    g_rk[((size_t)h * L2 + r) * Kdim + kk] = acc;
}

// ---------------- row softmax (float4 + shuffle), in-place on g_logits -----------
__global__ void softmax_kernel()
{
    const size_t row = blockIdx.x;
    float4* p = (float4*)(g_logits + row * Tdim);
    const int tid = threadIdx.x;     // 128 threads, 3 float4 each
    __shared__ float red[4];

    float4 v[3];
    float m = -1e30f;
    #pragma unroll
    for (int e = 0; e < 3; e++) {
        v[e] = p[tid + e * 128];
        m = fmaxf(m, fmaxf(fmaxf(v[e].x, v[e].y), fmaxf(v[e].z, v[e].w)));
    }
    #pragma unroll
    for (int o = 16; o > 0; o >>= 1) m = fmaxf(m, __shfl_xor_sync(0xffffffffu, m, o));
    if ((tid & 31) == 0) red[tid >> 5] = m;
    __syncthreads();
    m = fmaxf(fmaxf(red[0], red[1]), fmaxf(red[2], red[3]));
    __syncthreads();

    float s = 0.f;
    #pragma unroll
    for (int e = 0; e < 3; e++) {
        v[e].x = __expf(v[e].x - m); v[e].y = __expf(v[e].y - m);
        v[e].z = __expf(v[e].z - m); v[e].w = __expf(v[e].w - m);
        s += v[e].x + v[e].y + v[e].z + v[e].w;
    }
    #pragma unroll
    for (int o = 16; o > 0; o >>= 1) s += __shfl_xor_sync(0xffffffffu, s, o);
    if ((tid & 31) == 0) red[tid >> 5] = s;
    __syncthreads();
    s = red[0] + red[1] + red[2] + red[3];
    float inv = 1.0f / s;
    #pragma unroll
    for (int e = 0; e < 3; e++) {
        v[e].x *= inv; v[e].y *= inv; v[e].z *= inv; v[e].w *= inv;
        p[tid + e * 128] = v[e];
    }
}

// ---------------- launch ----------------------------------------------------------
extern "C" void kernel_launch(void* const* d_in, const int* in_sizes, int n_in,
                              void* d_out, int out_size)
{
    const float* x   = (const float*)d_in[0];
    const float* Wq  = (const float*)d_in[1];
    const float* Wk  = (const float*)d_in[2];
    const float* Wv  = (const float*)d_in[3];
    const float* Wr  = (const float*)d_in[4];
    const float* rwb = (const float*)d_in[5];
    const float* rrb = (const float*)d_in[6];
    const float* Wo  = (const float*)d_in[7];
    const float* bo  = (const float*)d_in[8];
    float* out = (float*)d_out;

    dim3 blk(256);
    // projections: M=3072
    mma_gemm<0, false><<<dim3(HK / 64, 24, 1), blk>>>(x, Wq, rwb, rrb, nullptr, Cdim, Cdim, HK);
    mma_gemm<1, false><<<dim3(HK / 64, 24, 1), blk>>>(x, Wk, nullptr, nullptr, nullptr, Cdim, Cdim, HK);
    mma_gemm<2, false><<<dim3(HV / 64, 24, 1), blk>>>(x, Wv, nullptr, nullptr, nullptr, Cdim, Cdim, HV);

    rk_kernel<<<L2, HK>>>(Wr);

    // content logits: [T,T] per (b,h)
    mma_gemm<5, true><<<dim3(Tdim / 64, Tdim / 128, Bdim * Hdim), blk>>>(
        nullptr, nullptr, nullptr, nullptr, nullptr, Kdim, Kdim, Kdim);
    // relative logits: banded r-space GEMM, scatter-add into logits
    mma_gemm<6, true><<<dim3(26, Tdim / 128, Bdim * Hdim), blk>>>(
        nullptr, nullptr, nullptr, nullptr, nullptr, Kdim, Kdim, Kdim);

    softmax_kernel<<<Bdim * Hdim * Tdim, 128>>>();

    // P @ V
    mma_gemm<4, false><<<dim3(Vdim / 64, Tdim / 128, Bdim * Hdim), blk>>>(
        nullptr, nullptr, nullptr, nullptr, nullptr, Tdim, Tdim, Vdim);

    // out proj
    mma_gemm<3, false><<<dim3(HV / 64, 24, 1), blk>>>(
        nullptr, Wo, bo, nullptr, out, HV, HV, HV);
}

// round 5
// speedup vs baseline: 2.0636x; 1.0383x over previous
#include <cuda_runtime.h>
#include <cuda_bf16.h>
#include <stdint.h>
#include <math.h>

// Problem constants
#define Bdim 2
#define Tdim 1536
#define Cdim 1536
#define Hdim 8
#define Kdim 64
#define Vdim 192
#define HK   512
#define HV   1536
#define L2   3071     // 2*T-1
#define ZN   16       // B*H

// pair counts
#define CP   768      // 1536/2 (c, s, t, hv pairs)
#define KP   32       // 64/2

// ---------------- scratch: packed bf16x2 hi/lo, [row][kpair] ----------------
__device__ uint32_t xs_h[(size_t)3072 * CP],  xs_l[(size_t)3072 * CP];     // x    [bt][cpair]
__device__ uint32_t wq_h[(size_t)HK * CP],    wq_l[(size_t)HK * CP];       // Wq^T [n][cpair]
__device__ uint32_t wk_h[(size_t)HK * CP],    wk_l[(size_t)HK * CP];
__device__ uint32_t wv_h[(size_t)HV * CP],    wv_l[(size_t)HV * CP];
__device__ uint32_t wo_h[(size_t)HV * CP],    wo_l[(size_t)HV * CP];
__device__ uint32_t qw_h[(size_t)ZN * Tdim * KP], qw_l[(size_t)ZN * Tdim * KP];
__device__ uint32_t qr_h[(size_t)ZN * Tdim * KP], qr_l[(size_t)ZN * Tdim * KP];
__device__ uint32_t kk_h[(size_t)ZN * Tdim * KP], kk_l[(size_t)ZN * Tdim * KP];
__device__ uint32_t rk_h[(size_t)Hdim * L2 * KP], rk_l[(size_t)Hdim * L2 * KP];
__device__ float    g_v [(size_t)ZN * Tdim * Vdim];                         // fp32, repacked below
__device__ uint32_t vt_h[(size_t)ZN * Vdim * CP], vt_l[(size_t)ZN * Vdim * CP]; // V^T [z][v][tpair]
__device__ uint32_t p_h [(size_t)ZN * Tdim * CP], p_l [(size_t)ZN * Tdim * CP]; // P  [z][t][spair]
__device__ uint32_t at_h[(size_t)3072 * CP],  at_l[(size_t)3072 * CP];     // attn [bt][hvpair]
__device__ float    g_logits[(size_t)ZN * Tdim * Tdim];

// ---------------- helpers ----------------
__device__ __forceinline__ uint32_t pack2(float a, float b) {
    uint32_t r;
    asm("cvt.rn.bf16x2.f32 %0, %1, %2;" : "=r"(r) : "f"(b), "f"(a));
    return r;
}
__device__ __forceinline__ void split2(float x0, float x1, uint32_t& h, uint32_t& l) {
    float h0 = __bfloat162float(__float2bfloat16(x0));
    float h1 = __bfloat162float(__float2bfloat16(x1));
    h = pack2(h0, h1);
    l = pack2(x0 - h0, x1 - h1);
}
__device__ __forceinline__ void mma_bf16(float* d, const uint32_t* a, const uint32_t* b) {
    asm volatile(
        "mma.sync.aligned.m16n8k16.row.col.f32.bf16.bf16.f32 "
        "{%0,%1,%2,%3}, {%4,%5,%6,%7}, {%8,%9}, {%0,%1,%2,%3};"
        : "+f"(d[0]), "+f"(d[1]), "+f"(d[2]), "+f"(d[3])
        : "r"(a[0]), "r"(a[1]), "r"(a[2]), "r"(a[3]), "r"(b[0]), "r"(b[1]));
}
__device__ __forceinline__ void cpa16(uint32_t dst, const void* src) {
    asm volatile("cp.async.cg.shared.global [%0], [%1], 16;" :: "r"(dst), "l"(src));
}
#define CP_COMMIT() asm volatile("cp.async.commit_group;")
#define CP_WAIT1()  asm volatile("cp.async.wait_group 1;")
#define CP_WAIT0()  asm volatile("cp.async.wait_group 0;")

// ---------------- prep: row split (x) ----------------
__global__ void split_rows(const float* __restrict__ in, uint32_t* __restrict__ oh,
                           uint32_t* __restrict__ ol, size_t npairs)
{
    size_t i = (size_t)blockIdx.x * blockDim.x + threadIdx.x;
    if (i >= npairs) return;
    float2 v = ((const float2*)in)[i];
    split2(v.x, v.y, oh[i], ol[i]);
}

// ---------------- prep: split + transpose  in[K][N] -> out[N][K/2 pairs] ----------
__global__ void split_T(const float* __restrict__ in, uint32_t* __restrict__ oh,
                        uint32_t* __restrict__ ol, int Kc, int N,
                        size_t in_zs, size_t out_zs)
{
    __shared__ float tile[32][33];
    const float* inz = in + (size_t)blockIdx.z * in_zs;
    uint32_t* ohz = oh + (size_t)blockIdx.z * out_zs;
    uint32_t* olz = ol + (size_t)blockIdx.z * out_zs;
    int k0 = blockIdx.y * 32, n0 = blockIdx.x * 32;
    int tid = threadIdx.x;
    #pragma unroll
    for (int i = 0; i < 4; i++) {
        int idx = tid + i * 256;
        int kr = idx >> 5, nn = idx & 31;
        tile[kr][nn] = inz[(size_t)(k0 + kr) * N + n0 + nn];
    }
    __syncthreads();
    #pragma unroll
    for (int i = 0; i < 2; i++) {
        int idx = tid + i * 256;
        int nn = idx >> 4, kp = idx & 15;
        uint32_t h, l;
        split2(tile[2 * kp][nn], tile[2 * kp + 1][nn], h, l);
        size_t o = (size_t)(n0 + nn) * (Kc / 2) + k0 / 2 + kp;
        ohz[o] = h; olz[o] = l;
    }
}

// ---------------- unified bf16x3 GEMM: 128x64 tile, k-chunk 16, cp.async x2 ------
// MODE 0: x@Wq -> qw,qr | 1: x@Wk -> k | 2: x@Wv -> g_v(fp32) | 3: attn@Wo+bo -> out
// MODE 4: P@V -> at_h/l | 5: qw@k^T -> logits | 6: qr@rk^T banded scatter-add
template <int MODE>
__global__ __launch_bounds__(256) void mma_gemm(
    const float* __restrict__ bias0, const float* __restrict__ bias1,
    float* __restrict__ outp)
{
    __shared__ uint32_t sm[2 * 4608];  // per stage: Ah[1536] Al[1536] Bh[768] Bl[768]

    const int z   = blockIdx.z;
    const int m0  = blockIdx.y * 128;
    const int n0  = blockIdx.x * 64;
    const int tid = threadIdx.x;
    const int lane = tid & 31, warp = tid >> 5;
    const int wm = warp >> 1, wn = warp & 1;

    const uint32_t *Ah, *Al, *Bh, *Bl;
    int ldpA, ldpB, Kc;
    if (MODE == 0) { Ah = xs_h; Al = xs_l; Bh = wq_h; Bl = wq_l; ldpA = CP; ldpB = CP; Kc = Cdim; }
    else if (MODE == 1) { Ah = xs_h; Al = xs_l; Bh = wk_h; Bl = wk_l; ldpA = CP; ldpB = CP; Kc = Cdim; }
    else if (MODE == 2) { Ah = xs_h; Al = xs_l; Bh = wv_h; Bl = wv_l; ldpA = CP; ldpB = CP; Kc = Cdim; }
    else if (MODE == 3) { Ah = at_h; Al = at_l; Bh = wo_h; Bl = wo_l; ldpA = CP; ldpB = CP; Kc = HV; }
    else if (MODE == 4) { Ah = p_h + (size_t)z * Tdim * CP; Al = p_l + (size_t)z * Tdim * CP;
                          Bh = vt_h + (size_t)z * Vdim * CP; Bl = vt_l + (size_t)z * Vdim * CP;
                          ldpA = CP; ldpB = CP; Kc = Tdim; }
    else if (MODE == 5) { Ah = qw_h + (size_t)z * Tdim * KP; Al = qw_l + (size_t)z * Tdim * KP;
                          Bh = kk_h + (size_t)z * Tdim * KP; Bl = kk_l + (size_t)z * Tdim * KP;
                          ldpA = KP; ldpB = KP; Kc = Kdim; }
    else                { Ah = qr_h + (size_t)z * Tdim * KP; Al = qr_l + (size_t)z * Tdim * KP;
                          Bh = rk_h + (size_t)(z & 7) * L2 * KP; Bl = rk_l + (size_t)(z & 7) * L2 * KP;
                          ldpA = KP; ldpB = KP; Kc = Kdim; }

    const int rbase = (MODE == 6) ? (1408 - m0 + n0) : n0;

    const uint32_t smb = (uint32_t)__cvta_generic_to_shared(sm);
    // per-thread load assignments (fixed across chunks)
    const int arow = tid >> 1, ahalf = tid & 1;
    const int brow = (tid & 127) >> 1, bhalf = tid & 1;
    int bgr = rbase + brow;
    if (MODE == 6 && bgr > L2 - 1) bgr = L2 - 1;
    const uint32_t* Bsel = (tid < 128) ? Bh : Bl;
    const size_t asrc_h = (size_t)(m0 + arow) * ldpA + ahalf * 4;
    const size_t bsrc   = (size_t)bgr * ldpB + bhalf * 4;
    const uint32_t adst  = smb + (uint32_t)(arow * 12 + ahalf * 4) * 4;
    const uint32_t bdst  = smb + (uint32_t)(3072 + ((tid < 128) ? 0 : 768) + brow * 12 + bhalf * 4) * 4;

    const int nchunks = Kc / 16;
    float acc[2][4][4] = {};

    // prologue: stage 0
    {
        cpa16(adst,          Ah + asrc_h);
        cpa16(adst + 1536*4, Al + asrc_h);
        cpa16(bdst,          Bsel + bsrc);
        CP_COMMIT();
    }

    for (int c = 0; c < nchunks; c++) {
        if (c + 1 < nchunks) {
            const int st = (c + 1) & 1;
            const int kcp = (c + 1) * 8;
            cpa16(adst + st * 4608 * 4,          Ah + asrc_h + kcp);
            cpa16(adst + (st * 4608 + 1536) * 4, Al + asrc_h + kcp);
            cpa16(bdst + st * 4608 * 4,          Bsel + bsrc + kcp);
            CP_COMMIT();
            CP_WAIT1();
        } else {
            CP_WAIT0();
        }
        __syncthreads();

        const uint32_t* Ah_s = sm + (c & 1) * 4608;
        const uint32_t* Al_s = Ah_s + 1536;
        const uint32_t* Bh_s = Ah_s + 3072;
        const uint32_t* Bl_s = Ah_s + 3840;

        const int kp  = lane & 3;
        const int ar0 = wm * 32 + (lane >> 2);
        uint32_t ah[2][4], al[2][4], bh[4][2], bl[4][2];
        #pragma unroll
        for (int mi = 0; mi < 2; mi++) {
            int r = ar0 + mi * 16;
            ah[mi][0] = Ah_s[r * 12 + kp];       ah[mi][1] = Ah_s[(r + 8) * 12 + kp];
            ah[mi][2] = Ah_s[r * 12 + kp + 4];   ah[mi][3] = Ah_s[(r + 8) * 12 + kp + 4];
            al[mi][0] = Al_s[r * 12 + kp];       al[mi][1] = Al_s[(r + 8) * 12 + kp];
            al[mi][2] = Al_s[r * 12 + kp + 4];   al[mi][3] = Al_s[(r + 8) * 12 + kp + 4];
        }
        #pragma unroll
        for (int ni = 0; ni < 4; ni++) {
            int n = wn * 32 + ni * 8 + (lane >> 2);
            bh[ni][0] = Bh_s[n * 12 + kp];  bh[ni][1] = Bh_s[n * 12 + kp + 4];
            bl[ni][0] = Bl_s[n * 12 + kp];  bl[ni][1] = Bl_s[n * 12 + kp + 4];
        }
        #pragma unroll
        for (int mi = 0; mi < 2; mi++)
            #pragma unroll
            for (int ni = 0; ni < 4; ni++) {
                mma_bf16(acc[mi][ni], ah[mi], bh[ni]);
                mma_bf16(acc[mi][ni], ah[mi], bl[ni]);
                mma_bf16(acc[mi][ni], al[mi], bh[ni]);
            }
        __syncthreads();
    }

    // ---------------- epilogue ----------------
    #pragma unroll
    for (int mi = 0; mi < 2; mi++) {
        #pragma unroll
        for (int ni = 0; ni < 4; ni++) {
            #pragma unroll
            for (int hh = 0; hh < 2; hh++) {
                const int row = m0 + wm * 32 + mi * 16 + (lane >> 2) + hh * 8;
                const int col = rbase + wn * 32 + ni * 8 + 2 * (lane & 3);
                float v0 = acc[mi][ni][hh * 2 + 0];
                float v1 = acc[mi][ni][hh * 2 + 1];

                if (MODE == 0) {
                    int bb = row / Tdim, t = row % Tdim;
                    int h = col >> 6, kw = col & 63;
                    size_t idx = (((size_t)(bb * Hdim + h)) * Tdim + t) * KP + (kw >> 1);
                    float q0 = v0 * 0.125f, q1 = v1 * 0.125f;
                    uint32_t hw, lw;
                    split2(q0 + bias0[col], q1 + bias0[col + 1], hw, lw);
                    qw_h[idx] = hw; qw_l[idx] = lw;
                    split2(q0 + bias1[col], q1 + bias1[col + 1], hw, lw);
                    qr_h[idx] = hw; qr_l[idx] = lw;
                } else if (MODE == 1) {
                    int bb = row / Tdim, t = row % Tdim;
                    int h = col >> 6, kw = col & 63;
                    size_t idx = (((size_t)(bb * Hdim + h)) * Tdim + t) * KP + (kw >> 1);
                    uint32_t hw, lw;
                    split2(v0, v1, hw, lw);
                    kk_h[idx] = hw; kk_l[idx] = lw;
                } else if (MODE == 2) {
                    int bb = row / Tdim, t = row % Tdim;
                    int h = col / Vdim, vv = col % Vdim;
                    *(float2*)&g_v[(((size_t)(bb * Hdim + h)) * Tdim + t) * Vdim + vv] = make_float2(v0, v1);
                } else if (MODE == 3) {
                    *(float2*)&outp[(size_t)row * HV + col] = make_float2(v0 + bias0[col], v1 + bias0[col + 1]);
                } else if (MODE == 4) {
                    int bb = z >> 3, h = z & 7;
                    int hv = h * Vdim + col;
                    size_t idx = (size_t)(bb * Tdim + row) * CP + (hv >> 1);
                    uint32_t hw, lw;
                    split2(v0, v1, hw, lw);
                    at_h[idx] = hw; at_l[idx] = lw;
                } else if (MODE == 5) {
                    *(float2*)&g_logits[((size_t)z * Tdim + row) * Tdim + col] = make_float2(v0, v1);
                } else { // MODE 6 scatter-add: s = r + t - (T-1)
                    float* pl = g_logits + ((size_t)z * Tdim + row) * Tdim;
                    int s0 = col + row - (Tdim - 1);
                    if (s0 >= 0 && s0 < Tdim) pl[s0] += v0;
                    if (s0 + 1 >= 0 && s0 + 1 < Tdim) pl[s0 + 1] += v1;
                }
            }
        }
    }
}

// ---------------- positional features @ Wr -> rk_h/l [h][r][kpair] ---------------
__global__ void rk_kernel(const float* __restrict__ Wr)
{
    __shared__ float cw[16];
    int r = blockIdx.x;
    int tid = threadIdx.x;                  // 256: h = tid>>5, kp = tid&31
    if (tid < 16) {
        float pr = (float)exp(log((double)(Tdim + 1)) / 16.0);
        cw[tid] = powf(pr, (float)(tid + 1)) - 1.0f;
    }
    __syncthreads();
    float d  = (float)(r - (Tdim - 1));
    float ad = fabsf(d);
    float sg = (d > 0.f) ? 1.f : ((d < 0.f) ? -1.f : 0.f);
    int h = tid >> 5, kp = tid & 31;
    int c0 = h * 64 + 2 * kp;
    float a0 = 0.f, a1 = 0.f;
    #pragma unroll
    for (int i = 0; i < 16; i++)
        if (cw[i] > ad) {
            a0 += Wr[i * HK + c0]     + sg * Wr[(i + 16) * HK + c0];
            a1 += Wr[i * HK + c0 + 1] + sg * Wr[(i + 16) * HK + c0 + 1];
        }
    uint32_t hw, lw;
    split2(a0, a1, hw, lw);
    size_t idx = ((size_t)h * L2 + r) * KP + kp;
    rk_h[idx] = hw; rk_l[idx] = lw;
}

// ---------------- row softmax: read logits fp32, write P split bf16 --------------
__global__ void softmax_kernel()
{
    const size_t row = blockIdx.x;
    const float4* p = (const float4*)(g_logits + row * Tdim);
    uint32_t* ph = p_h + row * CP;
    uint32_t* plo = p_l + row * CP;
    const int tid = threadIdx.x;     // 128 threads, 3 float4 each
    __shared__ float red[4];

    float4 v[3];
    float m = -1e30f;
    #pragma unroll
    for (int e = 0; e < 3; e++) {
        v[e] = p[tid + e * 128];
        m = fmaxf(m, fmaxf(fmaxf(v[e].x, v[e].y), fmaxf(v[e].z, v[e].w)));
    }
    #pragma unroll
    for (int o = 16; o > 0; o >>= 1) m = fmaxf(m, __shfl_xor_sync(0xffffffffu, m, o));
    if ((tid & 31) == 0) red[tid >> 5] = m;
    __syncthreads();
    m = fmaxf(fmaxf(red[0], red[1]), fmaxf(red[2], red[3]));
    __syncthreads();

    float s = 0.f;
    #pragma unroll
    for (int e = 0; e < 3; e++) {
        v[e].x = __expf(v[e].x - m); v[e].y = __expf(v[e].y - m);
        v[e].z = __expf(v[e].z - m); v[e].w = __expf(v[e].w - m);
        s += v[e].x + v[e].y + v[e].z + v[e].w;
    }
    #pragma unroll
    for (int o = 16; o > 0; o >>= 1) s += __shfl_xor_sync(0xffffffffu, s, o);
    if ((tid & 31) == 0) red[tid >> 5] = s;
    __syncthreads();
    s = red[0] + red[1] + red[2] + red[3];
    float inv = 1.0f / s;
    #pragma unroll
    for (int e = 0; e < 3; e++) {
        float p0 = v[e].x * inv, p1 = v[e].y * inv, p2 = v[e].z * inv, p3 = v[e].w * inv;
        uint32_t h0, l0, h1, l1;
        split2(p0, p1, h0, l0);
        split2(p2, p3, h1, l1);
        int o = (tid + e * 128) * 2;
        *(uint2*)&ph[o]  = make_uint2(h0, h1);
        *(uint2*)&plo[o] = make_uint2(l0, l1);
    }
}

// ---------------- launch ----------------------------------------------------------
extern "C" void kernel_launch(void* const* d_in, const int* in_sizes, int n_in,
                              void* d_out, int out_size)
{
    const float* x   = (const float*)d_in[0];
    const float* Wq  = (const float*)d_in[1];
    const float* Wk  = (const float*)d_in[2];
    const float* Wv  = (const float*)d_in[3];
    const float* Wr  = (const float*)d_in[4];
    const float* rwb = (const float*)d_in[5];
    const float* rrb = (const float*)d_in[6];
    const float* Wo  = (const float*)d_in[7];
    const float* bo  = (const float*)d_in[8];
    float* out = (float*)d_out;

    uint32_t *d_xs_h, *d_xs_l, *d_wq_h, *d_wq_l, *d_wk_h, *d_wk_l;
    uint32_t *d_wv_h, *d_wv_l, *d_wo_h, *d_wo_l, *d_vt_h, *d_vt_l;
    float* d_gv;
    cudaGetSymbolAddress((void**)&d_xs_h, xs_h); cudaGetSymbolAddress((void**)&d_xs_l, xs_l);
    cudaGetSymbolAddress((void**)&d_wq_h, wq_h); cudaGetSymbolAddress((void**)&d_wq_l, wq_l);
    cudaGetSymbolAddress((void**)&d_wk_h, wk_h); cudaGetSymbolAddress((void**)&d_wk_l, wk_l);
    cudaGetSymbolAddress((void**)&d_wv_h, wv_h); cudaGetSymbolAddress((void**)&d_wv_l, wv_l);
    cudaGetSymbolAddress((void**)&d_wo_h, wo_h); cudaGetSymbolAddress((void**)&d_wo_l, wo_l);
    cudaGetSymbolAddress((void**)&d_vt_h, vt_h); cudaGetSymbolAddress((void**)&d_vt_l, vt_l);
    cudaGetSymbolAddress((void**)&d_gv, g_v);

    // prep: split inputs
    split_rows<<<(3072 * CP + 255) / 256, 256>>>(x, d_xs_h, d_xs_l, (size_t)3072 * CP);
    split_T<<<dim3(HK / 32, Cdim / 32, 1), 256>>>(Wq, d_wq_h, d_wq_l, Cdim, HK, 0, 0);
    split_T<<<dim3(HK / 32, Cdim / 32, 1), 256>>>(Wk, d_wk_h, d_wk_l, Cdim, HK, 0, 0);
    split_T<<<dim3(HV / 32, Cdim / 32, 1), 256>>>(Wv, d_wv_h, d_wv_l, Cdim, HV, 0, 0);
    split_T<<<dim3(HV / 32, HV / 32, 1), 256>>>(Wo, d_wo_h, d_wo_l, HV, HV, 0, 0);
    rk_kernel<<<L2, 256>>>(Wr);

    // projections
    mma_gemm<0><<<dim3(HK / 64, 24, 1), 256>>>(rwb, rrb, nullptr);
    mma_gemm<1><<<dim3(HK / 64, 24, 1), 256>>>(nullptr, nullptr, nullptr);
    mma_gemm<2><<<dim3(HV / 64, 24, 1), 256>>>(nullptr, nullptr, nullptr);

    // V repack: [z][t][v] -> [z][v][tpair]
    split_T<<<dim3(Vdim / 32, Tdim / 32, ZN), 256>>>(d_gv, d_vt_h, d_vt_l, Tdim, Vdim,
                                                     (size_t)Tdim * Vdim, (size_t)Vdim * CP);

    // logits
    mma_gemm<5><<<dim3(Tdim / 64, Tdim / 128, ZN), 256>>>(nullptr, nullptr, nullptr);
    mma_gemm<6><<<dim3(26, Tdim / 128, ZN), 256>>>(nullptr, nullptr, nullptr);

    softmax_kernel<<<ZN * Tdim, 128>>>();

    // P @ V
    mma_gemm<4><<<dim3(Vdim / 64, Tdim / 128, ZN), 256>>>(nullptr, nullptr, nullptr);

    // out proj
    mma_gemm<3><<<dim3(HV / 64, 24, 1), 256>>>(bo, nullptr, out);
}

// round 7
// speedup vs baseline: 2.2730x; 1.1015x over previous
#include <cuda_runtime.h>
#include <cuda_bf16.h>
#include <stdint.h>
#include <math.h>

// Problem constants
#define Bdim 2
#define Tdim 1536
#define Cdim 1536
#define Hdim 8
#define Kdim 64
#define Vdim 192
#define HK   512
#define HV   1536
#define L2   3071     // 2*T-1
#define ZN   16       // B*H
#define CP   768      // 1536/2 pairs
#define KP   32       // 64/2 pairs

// ---------------- scratch: packed bf16x2 hi/lo, [row][kpair] ----------------
__device__ uint32_t xs_h[(size_t)3072 * CP],  xs_l[(size_t)3072 * CP];
__device__ uint32_t wq_h[(size_t)HK * CP],    wq_l[(size_t)HK * CP];
__device__ uint32_t wk_h[(size_t)HK * CP],    wk_l[(size_t)HK * CP];
__device__ uint32_t wv_h[(size_t)HV * CP],    wv_l[(size_t)HV * CP];
__device__ uint32_t wo_h[(size_t)HV * CP],    wo_l[(size_t)HV * CP];
__device__ uint32_t qw_h[(size_t)ZN * Tdim * KP], qw_l[(size_t)ZN * Tdim * KP];
__device__ uint32_t qr_h[(size_t)ZN * Tdim * KP], qr_l[(size_t)ZN * Tdim * KP];
__device__ uint32_t kk_h[(size_t)ZN * Tdim * KP], kk_l[(size_t)ZN * Tdim * KP];
__device__ uint32_t rk_h[(size_t)Hdim * L2 * KP], rk_l[(size_t)Hdim * L2 * KP];
__device__ float    g_v [(size_t)ZN * Tdim * Vdim];
__device__ uint32_t vt_h[(size_t)ZN * Vdim * CP], vt_l[(size_t)ZN * Vdim * CP];
__device__ uint32_t p_h [(size_t)ZN * Tdim * CP], p_l [(size_t)ZN * Tdim * CP];
__device__ uint32_t at_h[(size_t)3072 * CP],  at_l[(size_t)3072 * CP];
__device__ float    g_logits[(size_t)ZN * Tdim * Tdim];

// ---------------- helpers ----------------
__device__ __forceinline__ uint32_t pack2(float a, float b) {
    uint32_t r;
    asm("cvt.rn.bf16x2.f32 %0, %1, %2;" : "=r"(r) : "f"(b), "f"(a));
    return r;
}
__device__ __forceinline__ void split2(float x0, float x1, uint32_t& h, uint32_t& l) {
    float h0 = __bfloat162float(__float2bfloat16(x0));
    float h1 = __bfloat162float(__float2bfloat16(x1));
    h = pack2(h0, h1);
    l = pack2(x0 - h0, x1 - h1);
}
__device__ __forceinline__ void mma_bf16(float* d, const uint32_t* a, const uint32_t* b) {
    asm volatile(
        "mma.sync.aligned.m16n8k16.row.col.f32.bf16.bf16.f32 "
        "{%0,%1,%2,%3}, {%4,%5,%6,%7}, {%8,%9}, {%0,%1,%2,%3};"
        : "+f"(d[0]), "+f"(d[1]), "+f"(d[2]), "+f"(d[3])
        : "r"(a[0]), "r"(a[1]), "r"(a[2]), "r"(a[3]), "r"(b[0]), "r"(b[1]));
}
__device__ __forceinline__ void cpa16(uint32_t dst, const void* src) {
    asm volatile("cp.async.cg.shared.global [%0], [%1], 16;" :: "r"(dst), "l"(src));
}
#define CP_COMMIT() asm volatile("cp.async.commit_group;")
__device__ __forceinline__ void ldm4(uint32_t* r, uint32_t addr) {
    asm volatile("ldmatrix.sync.aligned.m8n8.x4.shared.b16 {%0,%1,%2,%3}, [%4];"
                 : "=r"(r[0]), "=r"(r[1]), "=r"(r[2]), "=r"(r[3]) : "r"(addr));
}

// ---------------- mma.sync bf16x3 GEMM: 128x64 tile, k-chunk 32, ldmatrix --------
// smem stage layout (bytes): Ah[128*80] Al[128*80] Bh[64*80] Bl[64*80]
#define AROWB 80
#define A_LO  10240
#define B_OFF 20480
#define B_LO  5120
#define STG   30720
#define SMEM_REQ (2 * STG)

// MODE 0: x@Wq -> qw,qr | 1: x@Wk -> kk | 2: x@Wv -> g_v | 3: attn@Wo+bo -> out
// MODE 4: P@V -> at | 5: qw@k^T -> logits | 6: qr@rk^T banded scatter-add
template <int MODE>
__global__ __launch_bounds__(256) void mma_gemm(
    const float* __restrict__ bias0, const float* __restrict__ bias1,
    float* __restrict__ outp)
{
    extern __shared__ uint8_t dsm[];

    const int z   = blockIdx.z;
    const int m0  = blockIdx.y * 128;
    const int n0  = blockIdx.x * 64;
    const int tid = threadIdx.x;
    const int lane = tid & 31, warp = tid >> 5;
    const int wm = warp >> 1, wn = warp & 1;

    const uint32_t *Ah_g, *Al_g, *Bh_g, *Bl_g;
    int ldpA, ldpB, nchunks;
    if (MODE == 0) { Ah_g = xs_h; Al_g = xs_l; Bh_g = wq_h; Bl_g = wq_l; ldpA = CP; ldpB = CP; nchunks = Cdim / 32; }
    else if (MODE == 1) { Ah_g = xs_h; Al_g = xs_l; Bh_g = wk_h; Bl_g = wk_l; ldpA = CP; ldpB = CP; nchunks = Cdim / 32; }
    else if (MODE == 2) { Ah_g = xs_h; Al_g = xs_l; Bh_g = wv_h; Bl_g = wv_l; ldpA = CP; ldpB = CP; nchunks = Cdim / 32; }
    else if (MODE == 3) { Ah_g = at_h; Al_g = at_l; Bh_g = wo_h; Bl_g = wo_l; ldpA = CP; ldpB = CP; nchunks = HV / 32; }
    else if (MODE == 4) { Ah_g = p_h + (size_t)z * Tdim * CP; Al_g = p_l + (size_t)z * Tdim * CP;
                          Bh_g = vt_h + (size_t)z * Vdim * CP; Bl_g = vt_l + (size_t)z * Vdim * CP;
                          ldpA = CP; ldpB = CP; nchunks = Tdim / 32; }
    else if (MODE == 5) { Ah_g = qw_h + (size_t)z * Tdim * KP; Al_g = qw_l + (size_t)z * Tdim * KP;
                          Bh_g = kk_h + (size_t)z * Tdim * KP; Bl_g = kk_l + (size_t)z * Tdim * KP;
                          ldpA = KP; ldpB = KP; nchunks = Kdim / 32; }
    else                { Ah_g = qr_h + (size_t)z * Tdim * KP; Al_g = qr_l + (size_t)z * Tdim * KP;
                          Bh_g = rk_h + (size_t)(z & 7) * L2 * KP; Bl_g = rk_l + (size_t)(z & 7) * L2 * KP;
                          ldpA = KP; ldpB = KP; nchunks = Kdim / 32; }

    const int rbase = (MODE == 6) ? (1408 - m0 + n0) : n0;

    const uint32_t sb = (uint32_t)__cvta_generic_to_shared(dsm);

    // ---- producer thread assignments (fixed) ----
    const int ar = tid >> 1, ac2 = (tid & 1) * 2;           // A: 2 chunks of 16B each iter
    const int br = tid >> 2, bc  = tid & 3;                 // B: 1 chunk
    int bgr = rbase + br;
    if (MODE == 6 && bgr > L2 - 1) bgr = L2 - 1;
    const size_t aoff0 = (size_t)(m0 + ar) * ldpA + ac2 * 4;
    const size_t boff0 = (size_t)bgr * ldpB + bc * 4;
    const uint32_t adst0 = sb + ar * AROWB + ac2 * 16;
    const uint32_t bdst0 = sb + B_OFF + br * AROWB + bc * 16;

    auto fill = [&](int s, int c) {
        const uint32_t st = s * STG;
        const size_t ko = (size_t)c * 16;
        cpa16(adst0 + st,               Ah_g + aoff0 + ko);
        cpa16(adst0 + st + 16,          Ah_g + aoff0 + ko + 4);
        cpa16(adst0 + st + A_LO,        Al_g + aoff0 + ko);
        cpa16(adst0 + st + A_LO + 16,   Al_g + aoff0 + ko + 4);
        cpa16(bdst0 + st,               Bh_g + boff0 + ko);
        cpa16(bdst0 + st + B_LO,        Bl_g + boff0 + ko);
        CP_COMMIT();
    };

    // ---- consumer lane addressing (ldmatrix) ----
    const int mat = lane >> 3, rIn = lane & 7;
    const int mrow = (mat & 1) * 8 + rIn;
    const int colb = (mat >> 1) * 16;
    const uint32_t aAddr = sb + (uint32_t)((wm * 32 + mrow) * AROWB + colb);
    const uint32_t bAddr = sb + (uint32_t)(B_OFF + (wn * 32 + mrow) * AROWB + colb);

    float acc[2][4][4] = {};

    fill(0, 0);
    if (nchunks > 1) fill(1, 1);

    for (int c = 0; c < nchunks; c++) {
        const int s = c & 1;
        if (c + 1 < nchunks) asm volatile("cp.async.wait_group 1;");
        else                 asm volatile("cp.async.wait_group 0;");
        __syncthreads();

        const uint32_t st = s * STG;
        #pragma unroll
        for (int kh = 0; kh < 2; kh++) {
            uint32_t ah[2][4], al[2][4], bh[2][4], bl[2][4];
            ldm4(ah[0], aAddr + st + kh * 32);
            ldm4(ah[1], aAddr + st + 16 * AROWB + kh * 32);
            ldm4(al[0], aAddr + st + A_LO + kh * 32);
            ldm4(al[1], aAddr + st + A_LO + 16 * AROWB + kh * 32);
            ldm4(bh[0], bAddr + st + kh * 32);
            ldm4(bh[1], bAddr + st + 16 * AROWB + kh * 32);
            ldm4(bl[0], bAddr + st + B_LO + kh * 32);
            ldm4(bl[1], bAddr + st + B_LO + 16 * AROWB + kh * 32);
            #pragma unroll
            for (int mi = 0; mi < 2; mi++)
                #pragma unroll
                for (int ni = 0; ni < 4; ni++) {
                    const int ng = ni >> 1, j = ni & 1;
                    uint32_t b2h[2] = { bh[ng][j], bh[ng][j + 2] };
                    uint32_t b2l[2] = { bl[ng][j], bl[ng][j + 2] };
                    mma_bf16(acc[mi][ni], ah[mi], b2h);
                    mma_bf16(acc[mi][ni], ah[mi], b2l);
                    mma_bf16(acc[mi][ni], al[mi], b2h);
                }
        }
        __syncthreads();
        if (c + 2 < nchunks) fill(s, c + 2);
    }

    // ---------------- epilogue (fragment mapping as R5) ----------------
    #pragma unroll
    for (int mi = 0; mi < 2; mi++) {
        #pragma unroll
        for (int ni = 0; ni < 4; ni++) {
            #pragma unroll
            for (int hh = 0; hh < 2; hh++) {
                const int row = m0 + wm * 32 + mi * 16 + (lane >> 2) + hh * 8;
                const int col = rbase + wn * 32 + ni * 8 + 2 * (lane & 3);
                float v0 = acc[mi][ni][hh * 2 + 0];
                float v1 = acc[mi][ni][hh * 2 + 1];

                if (MODE == 0) {
                    int bb = row / Tdim, t = row % Tdim;
                    int h = col >> 6, kw = col & 63;
                    size_t idx = (((size_t)(bb * Hdim + h)) * Tdim + t) * KP + (kw >> 1);
                    float q0 = v0 * 0.125f, q1 = v1 * 0.125f;
                    uint32_t hw, lw;
                    split2(q0 + bias0[col], q1 + bias0[col + 1], hw, lw);
                    qw_h[idx] = hw; qw_l[idx] = lw;
                    split2(q0 + bias1[col], q1 + bias1[col + 1], hw, lw);
                    qr_h[idx] = hw; qr_l[idx] = lw;
                } else if (MODE == 1) {
                    int bb = row / Tdim, t = row % Tdim;
                    int h = col >> 6, kw = col & 63;
                    size_t idx = (((size_t)(bb * Hdim + h)) * Tdim + t) * KP + (kw >> 1);
                    uint32_t hw, lw;
                    split2(v0, v1, hw, lw);
                    kk_h[idx] = hw; kk_l[idx] = lw;
                } else if (MODE == 2) {
                    int bb = row / Tdim, t = row % Tdim;
                    int h = col / Vdim, vv = col % Vdim;
                    *(float2*)&g_v[(((size_t)(bb * Hdim + h)) * Tdim + t) * Vdim + vv] = make_float2(v0, v1);
                } else if (MODE == 3) {
                    *(float2*)&outp[(size_t)row * HV + col] = make_float2(v0 + bias0[col], v1 + bias0[col + 1]);
                } else if (MODE == 4) {
                    int bb = z >> 3, h = z & 7;
                    int hv = h * Vdim + col;
                    size_t idx = (size_t)(bb * Tdim + row) * CP + (hv >> 1);
                    uint32_t hw, lw;
                    split2(v0, v1, hw, lw);
                    at_h[idx] = hw; at_l[idx] = lw;
                } else if (MODE == 5) {
                    *(float2*)&g_logits[((size_t)z * Tdim + row) * Tdim + col] = make_float2(v0, v1);
                } else { // MODE 6 scatter-add: s = r + t - (T-1)
                    float* pl = g_logits + ((size_t)z * Tdim + row) * Tdim;
                    int s0 = col + row - (Tdim - 1);
                    if (s0 >= 0 && s0 < Tdim) pl[s0] += v0;
                    if (s0 + 1 >= 0 && s0 + 1 < Tdim) pl[s0 + 1] += v1;
                }
            }
        }
    }
}

// ---------------- prep kernels ----------------
__global__ void split_rows(const float* __restrict__ in, uint32_t* __restrict__ oh,
                           uint32_t* __restrict__ ol, size_t npairs)
{
    size_t i = (size_t)blockIdx.x * blockDim.x + threadIdx.x;
    if (i >= npairs) return;
    float2 v = ((const float2*)in)[i];
    split2(v.x, v.y, oh[i], ol[i]);
}

__global__ void split_T(const float* __restrict__ in, uint32_t* __restrict__ oh,
                        uint32_t* __restrict__ ol, int Kc, int N,
                        size_t in_zs, size_t out_zs)
{
    __shared__ float tile[32][33];
    const float* inz = in + (size_t)blockIdx.z * in_zs;
    uint32_t* ohz = oh + (size_t)blockIdx.z * out_zs;
    uint32_t* olz = ol + (size_t)blockIdx.z * out_zs;
    int k0 = blockIdx.y * 32, n0 = blockIdx.x * 32;
    int tid = threadIdx.x;
    #pragma unroll
    for (int i = 0; i < 4; i++) {
        int idx = tid + i * 256;
        int kr = idx >> 5, nn = idx & 31;
        tile[kr][nn] = inz[(size_t)(k0 + kr) * N + n0 + nn];
    }
    __syncthreads();
    #pragma unroll
    for (int i = 0; i < 2; i++) {
        int idx = tid + i * 256;
        int nn = idx >> 4, kp = idx & 15;
        uint32_t h, l;
        split2(tile[2 * kp][nn], tile[2 * kp + 1][nn], h, l);
        size_t o = (size_t)(n0 + nn) * (Kc / 2) + k0 / 2 + kp;
        ohz[o] = h; olz[o] = l;
    }
}

__global__ void rk_kernel(const float* __restrict__ Wr)
{
    __shared__ float cw[16];
    int r = blockIdx.x;
    int tid = threadIdx.x;
    if (tid < 16) {
        float pr = (float)exp(log((double)(Tdim + 1)) / 16.0);
        cw[tid] = powf(pr, (float)(tid + 1)) - 1.0f;
    }
    __syncthreads();
    float d  = (float)(r - (Tdim - 1));
    float ad = fabsf(d);
    float sg = (d > 0.f) ? 1.f : ((d < 0.f) ? -1.f : 0.f);
    int h = tid >> 5, kp = tid & 31;
    int c0 = h * 64 + 2 * kp;
    float a0 = 0.f, a1 = 0.f;
    #pragma unroll
    for (int i = 0; i < 16; i++)
        if (cw[i] > ad) {
            a0 += Wr[i * HK + c0]     + sg * Wr[(i + 16) * HK + c0];
            a1 += Wr[i * HK + c0 + 1] + sg * Wr[(i + 16) * HK + c0 + 1];
        }
    uint32_t hw, lw;
    split2(a0, a1, hw, lw);
    size_t idx = ((size_t)h * L2 + r) * KP + kp;
    rk_h[idx] = hw; rk_l[idx] = lw;
}

__global__ void softmax_kernel()
{
    const size_t row = blockIdx.x;
    const float4* p = (const float4*)(g_logits + row * Tdim);
    uint32_t* ph = p_h + row * CP;
    uint32_t* plo = p_l + row * CP;
    const int tid = threadIdx.x;
    __shared__ float red[4];

    float4 v[3];
    float m = -1e30f;
    #pragma unroll
    for (int e = 0; e < 3; e++) {
        v[e] = p[tid + e * 128];
        m = fmaxf(m, fmaxf(fmaxf(v[e].x, v[e].y), fmaxf(v[e].z, v[e].w)));
    }
    #pragma unroll
    for (int o = 16; o > 0; o >>= 1) m = fmaxf(m, __shfl_xor_sync(0xffffffffu, m, o));
    if ((tid & 31) == 0) red[tid >> 5] = m;
    __syncthreads();
    m = fmaxf(fmaxf(red[0], red[1]), fmaxf(red[2], red[3]));
    __syncthreads();

    float s = 0.f;
    #pragma unroll
    for (int e = 0; e < 3; e++) {
        v[e].x = __expf(v[e].x - m); v[e].y = __expf(v[e].y - m);
        v[e].z = __expf(v[e].z - m); v[e].w = __expf(v[e].w - m);
        s += v[e].x + v[e].y + v[e].z + v[e].w;
    }
    #pragma unroll
    for (int o = 16; o > 0; o >>= 1) s += __shfl_xor_sync(0xffffffffu, s, o);
    if ((tid & 31) == 0) red[tid >> 5] = s;
    __syncthreads();
    s = red[0] + red[1] + red[2] + red[3];
    float inv = 1.0f / s;
    #pragma unroll
    for (int e = 0; e < 3; e++) {
        float p0 = v[e].x * inv, p1 = v[e].y * inv, p2 = v[e].z * inv, p3 = v[e].w * inv;
        uint32_t h0, l0, h1, l1;
        split2(p0, p1, h0, l0);
        split2(p2, p3, h1, l1);
        int o = (tid + e * 128) * 2;
        *(uint2*)&ph[o]  = make_uint2(h0, h1);
        *(uint2*)&plo[o] = make_uint2(l0, l1);
    }
}

// ---------------- launch ----------------------------------------------------------
extern "C" void kernel_launch(void* const* d_in, const int* in_sizes, int n_in,
                              void* d_out, int out_size)
{
    const float* x   = (const float*)d_in[0];
    const float* Wq  = (const float*)d_in[1];
    const float* Wk  = (const float*)d_in[2];
    const float* Wv  = (const float*)d_in[3];
    const float* Wr  = (const float*)d_in[4];
    const float* rwb = (const float*)d_in[5];
    const float* rrb = (const float*)d_in[6];
    const float* Wo  = (const float*)d_in[7];
    const float* bo  = (const float*)d_in[8];
    float* out = (float*)d_out;

    uint32_t *d_xs_h, *d_xs_l, *d_wq_h, *d_wq_l, *d_wk_h, *d_wk_l;
    uint32_t *d_wv_h, *d_wv_l, *d_wo_h, *d_wo_l, *d_vt_h, *d_vt_l;
    float* d_gv;
    cudaGetSymbolAddress((void**)&d_xs_h, xs_h); cudaGetSymbolAddress((void**)&d_xs_l, xs_l);
    cudaGetSymbolAddress((void**)&d_wq_h, wq_h); cudaGetSymbolAddress((void**)&d_wq_l, wq_l);
    cudaGetSymbolAddress((void**)&d_wk_h, wk_h); cudaGetSymbolAddress((void**)&d_wk_l, wk_l);
    cudaGetSymbolAddress((void**)&d_wv_h, wv_h); cudaGetSymbolAddress((void**)&d_wv_l, wv_l);
    cudaGetSymbolAddress((void**)&d_wo_h, wo_h); cudaGetSymbolAddress((void**)&d_wo_l, wo_l);
    cudaGetSymbolAddress((void**)&d_vt_h, vt_h); cudaGetSymbolAddress((void**)&d_vt_l, vt_l);
    cudaGetSymbolAddress((void**)&d_gv, g_v);

    cudaFuncSetAttribute(mma_gemm<0>, cudaFuncAttributeMaxDynamicSharedMemorySize, SMEM_REQ);
    cudaFuncSetAttribute(mma_gemm<1>, cudaFuncAttributeMaxDynamicSharedMemorySize, SMEM_REQ);
    cudaFuncSetAttribute(mma_gemm<2>, cudaFuncAttributeMaxDynamicSharedMemorySize, SMEM_REQ);
    cudaFuncSetAttribute(mma_gemm<3>, cudaFuncAttributeMaxDynamicSharedMemorySize, SMEM_REQ);
    cudaFuncSetAttribute(mma_gemm<4>, cudaFuncAttributeMaxDynamicSharedMemorySize, SMEM_REQ);
    cudaFuncSetAttribute(mma_gemm<5>, cudaFuncAttributeMaxDynamicSharedMemorySize, SMEM_REQ);
    cudaFuncSetAttribute(mma_gemm<6>, cudaFuncAttributeMaxDynamicSharedMemorySize, SMEM_REQ);

    // prep: split inputs
    split_rows<<<(3072 * CP + 255) / 256, 256>>>(x, d_xs_h, d_xs_l, (size_t)3072 * CP);
    split_T<<<dim3(HK / 32, Cdim / 32, 1), 256>>>(Wq, d_wq_h, d_wq_l, Cdim, HK, 0, 0);
    split_T<<<dim3(HK / 32, Cdim / 32, 1), 256>>>(Wk, d_wk_h, d_wk_l, Cdim, HK, 0, 0);
    split_T<<<dim3(HV / 32, Cdim / 32, 1), 256>>>(Wv, d_wv_h, d_wv_l, Cdim, HV, 0, 0);
    split_T<<<dim3(HV / 32, HV / 32, 1), 256>>>(Wo, d_wo_h, d_wo_l, HV, HV, 0, 0);
    rk_kernel<<<L2, 256>>>(Wr);

    // projections
    mma_gemm<0><<<dim3(HK / 64, 24, 1), 256, SMEM_REQ>>>(rwb, rrb, nullptr);
    mma_gemm<1><<<dim3(HK / 64, 24, 1), 256, SMEM_REQ>>>(nullptr, nullptr, nullptr);
    mma_gemm<2><<<dim3(HV / 64, 24, 1), 256, SMEM_REQ>>>(nullptr, nullptr, nullptr);

    // V repack: [z][t][v] -> [z][v][tpair]
    split_T<<<dim3(Vdim / 32, Tdim / 32, ZN), 256>>>(d_gv, d_vt_h, d_vt_l, Tdim, Vdim,
                                                     (size_t)Tdim * Vdim, (size_t)Vdim * CP);

    // logits
    mma_gemm<5><<<dim3(Tdim / 64, Tdim / 128, ZN), 256, SMEM_REQ>>>(nullptr, nullptr, nullptr);
    mma_gemm<6><<<dim3(26, Tdim / 128, ZN), 256, SMEM_REQ>>>(nullptr, nullptr, nullptr);

    softmax_kernel<<<ZN * Tdim, 128>>>();

    // P @ V
    mma_gemm<4><<<dim3(Vdim / 64, Tdim / 128, ZN), 256, SMEM_REQ>>>(nullptr, nullptr, nullptr);

    // out proj
    mma_gemm<3><<<dim3(HV / 64, 24, 1), 256, SMEM_REQ>>>(bo, nullptr, out);
}